// round 13
// baseline (speedup 1.0000x reference)
#include <cuda_runtime.h>
#include <cuda_fp16.h>
#include <cstdint>

// Problem constants (16 clips of 10 s @ 48 kHz)
#define N_SAMP  480000
#define NP1     480001          // envelope length per row
#define WIN     240             // 5 ms box filter
#define EPSF    1e-6f
#define EPSW    (240.0f * 1e-6f)   // eps on raw window sums
#define LN2     0.6931471805599453

// Tiling: 256 threads, 16 d-elements each; window offset 240 = 15 thread slots.
#define NTHR    256
#define EPT     16
#define T_OUT   3840            // envelope outputs per block (threads 0..239 x 16)
#define L_DV    (T_OUT + WIN - 1)   // 4079 valid d elements per tile
#define MAXB    16

// Scratch (zero-initialized at load; reset by last block each run)
struct RowAcc { double s1, s2; int m; int pad[3]; };
__device__ RowAcc       g_acc[MAXB];
__device__ unsigned int g_count;

struct SMF {
    float   baseP[NTHR], baseT[NTHR];   // per-thread exclusive prefix bases
    __half2 h2P[NTHR * 9];              // local prefixes, half2-packed, idx 9t+k
    __half2 h2T[NTHR * 9];
    float   wsP[8], wsT[8];
    float   red1[8], red2[8], red3[8];
    double  fin[MAXB];
    int     flag;
};

// Both signals' thread-local diffs; all 8 LDG.128 issued before any math.
// d[m]=|x[id]-x[id-1]|, id=j0-120+m, m in [m0,m0+16).
template<bool INTERIOR>
__device__ __forceinline__ void diffs2(const float* __restrict__ xp,
                                       const float* __restrict__ xt,
                                       int j0, int m0, int lane,
                                       float runP[EPT], float runT[EPT],
                                       float& sP, float& sT)
{
    if (INTERIOR) {
        float hP = 0.f, hT = 0.f;
        if (lane == 0) { hP = xp[j0 - 121 + m0]; hT = xt[j0 - 121 + m0]; }
        const float4* p4 = reinterpret_cast<const float4*>(xp + (j0 - 120 + m0));
        const float4* q4 = reinterpret_cast<const float4*>(xt + (j0 - 120 + m0));
        float4 A0 = p4[0], A1 = p4[1], A2 = p4[2], A3 = p4[3];
        float4 B0 = q4[0], B1 = q4[1], B2 = q4[2], B3 = q4[3];
        float eP[EPT] = { A0.x, A0.y, A0.z, A0.w,  A1.x, A1.y, A1.z, A1.w,
                          A2.x, A2.y, A2.z, A2.w,  A3.x, A3.y, A3.z, A3.w };
        float eT[EPT] = { B0.x, B0.y, B0.z, B0.w,  B1.x, B1.y, B1.z, B1.w,
                          B2.x, B2.y, B2.z, B2.w,  B3.x, B3.y, B3.z, B3.w };
        float pP = __shfl_up_sync(0xffffffffu, A3.w, 1);
        float pT = __shfl_up_sync(0xffffffffu, B3.w, 1);
        if (lane == 0) { pP = hP; pT = hT; }
        sP = 0.f; sT = 0.f;
        #pragma unroll
        for (int c = 0; c < EPT; c++) {
            sP += fabsf(eP[c] - pP); pP = eP[c]; runP[c] = sP;
            sT += fabsf(eT[c] - pT); pT = eT[c]; runT[c] = sT;
        }
    } else {
        float pP, pT;
        {
            int i = j0 - 121 + m0;
            bool v = (i >= 0 && i < N_SAMP);
            pP = v ? xp[i] : 0.f;
            pT = v ? xt[i] : 0.f;
        }
        sP = 0.f; sT = 0.f;
        #pragma unroll
        for (int c = 0; c < EPT; c++) {
            int i = j0 - 120 + m0 + c;             // x index == d index
            bool v  = (i >= 0 && i < N_SAMP);
            float cP = v ? xp[i] : 0.f;
            float cT = v ? xt[i] : 0.f;
            bool ok = (i >= 1) && (i < N_SAMP) && (m0 + c < L_DV);
            sP += ok ? fabsf(cP - pP) : 0.f; pP = cP; runP[c] = sP;
            sT += ok ? fabsf(cT - pT) : 0.f; pT = cT; runT[c] = sT;
        }
    }
}

__global__ __launch_bounds__(NTHR, 4)
void k_fused(const float* __restrict__ y_pred, const float* __restrict__ y_true,
             float* __restrict__ out, int B, double invcnt)
{
    __shared__ SMF sm;
    const int t = threadIdx.x, lane = t & 31, wid = t >> 5;
    const int row = blockIdx.y;
    const int j0  = blockIdx.x * T_OUT;
    const float* xp = y_pred + (size_t)row * N_SAMP;
    const float* xt = y_true + (size_t)row * N_SAMP;

    const bool interior = (blockIdx.x >= 1) && (blockIdx.x + 2 < gridDim.x);

    float runP[EPT], runT[EPT];
    float sP, sT;
    if (interior) diffs2<true >(xp, xt, j0, t * EPT, lane, runP, runT, sP, sT);
    else          diffs2<false>(xp, xt, j0, t * EPT, lane, runP, runT, sP, sT);

    // ---- One interleaved warp scan (two independent chains) ----
    float vP = sP, vT = sT;
    #pragma unroll
    for (int off = 1; off < 32; off <<= 1) {
        float uP = __shfl_up_sync(0xffffffffu, vP, off);
        float uT = __shfl_up_sync(0xffffffffu, vT, off);
        if (lane >= off) { vP += uP; vT += uT; }
    }
    if (lane == 31) { sm.wsP[wid] = vP; sm.wsT[wid] = vT; }
    __syncthreads();

    float baseP = vP - sP, baseT = vT - sT;
    #pragma unroll
    for (int w = 0; w < 7; w++)
        if (w < wid) { baseP += sm.wsP[w]; baseT += sm.wsT[w]; }

    // ---- Publish base (fp32, lane stride 1) + runs (half2, lane stride 9) ----
    sm.baseP[t] = baseP;
    sm.baseT[t] = baseT;
    {
        __half2* rp = &sm.h2P[9 * t];
        __half2* rt = &sm.h2T[9 * t];
        #pragma unroll
        for (int k = 0; k < 8; k++) {
            rp[k] = __floats2half2_rn(runP[2 * k], runP[2 * k + 1]);
            rt[k] = __floats2half2_rn(runT[2 * k], runT[2 * k + 1]);
        }
    }
    __syncthreads();

    // ---- Env + loss fused: S[c] = P_nb[16(t+15)+c] - P_own[16t+c] ----
    float s1 = 0.f, s2 = 0.f, mx = 0.f;
    if (t < T_OUT / EPT) {                          // t < 240
        float bNP = sm.baseP[t + 15];
        float bNT = sm.baseT[t + 15];
        float rnP[EPT], rnT[EPT];
        {
            const __half2* qp = &sm.h2P[9 * (t + 15)];
            const __half2* qt = &sm.h2T[9 * (t + 15)];
            #pragma unroll
            for (int k = 0; k < 8; k++) {
                float2 fp = __half22float2(qp[k]);
                float2 ft = __half22float2(qt[k]);
                rnP[2 * k] = fp.x; rnP[2 * k + 1] = fp.y;
                rnT[2 * k] = ft.x; rnT[2 * k + 1] = ft.y;
            }
        }
        #pragma unroll
        for (int c = 0; c < EPT; c++) {
            if (interior || (j0 + t * EPT + c < NP1)) {
                float Sp = (c ? bNP + rnP[c - 1] : bNP) - (c ? baseP + runP[c - 1] : baseP);
                float St = (c ? bNT + rnT[c - 1] : bNT) - (c ? baseT + runT[c - 1] : baseT);
                float df = fabsf(__log2f(Sp + EPSW) - __log2f(St + EPSW));
                s1 += df; s2 += df * St; mx = fmaxf(mx, St);
            }
        }
    }

    // ---- Block reduction of (S1, S2, M) ----
    #pragma unroll
    for (int off = 16; off > 0; off >>= 1) {
        s1 += __shfl_down_sync(0xffffffffu, s1, off);
        s2 += __shfl_down_sync(0xffffffffu, s2, off);
        mx  = fmaxf(mx, __shfl_down_sync(0xffffffffu, mx, off));
    }
    if (lane == 0) { sm.red1[wid] = s1; sm.red2[wid] = s2; sm.red3[wid] = mx; }
    __syncthreads();

    if (t == 0) {
        float a1 = 0.f, a2 = 0.f, am = 0.f;
        #pragma unroll
        for (int w = 0; w < 8; w++) {
            a1 += sm.red1[w]; a2 += sm.red2[w]; am = fmaxf(am, sm.red3[w]);
        }
        atomicAdd(&g_acc[row].s1, (double)a1 * LN2);   // log2 -> ln
        atomicAdd(&g_acc[row].s2, (double)a2 * LN2);
        atomicMax(&g_acc[row].m, __float_as_int(am));  // raw window-sum max, >= 0
        __threadfence();

        unsigned int total = gridDim.x * gridDim.y;
        unsigned int old = atomicAdd(&g_count, 1u);
        sm.flag = (old == total - 1u) ? 1 : 0;
    }
    __syncthreads();

    if (sm.flag) {
        // Last block: finalize in parallel, reset scratch for next replay.
        __threadfence();
        if (t < B) {
            volatile double* p1 = &g_acc[t].s1;
            volatile double* p2 = &g_acc[t].s2;
            volatile int*    pm = &g_acc[t].m;
            double S1 = *p1;                   // sum df            (true scale)
            double S2 = *p2;                   // sum df * S_t      (240x scale)
            float  M  = __int_as_float(*pm);   // 240 * true max
            sm.fin[t] = 0.2 * S1 + 0.8 * S2 / ((double)M + (double)EPSW);
            g_acc[t].s1 = 0.0; g_acc[t].s2 = 0.0; g_acc[t].m = 0;
        }
        __syncthreads();
        if (t == 0) {
            double tot = 0.0;
            for (int r = 0; r < B; r++) tot += sm.fin[r];
            out[0] = (float)(tot * invcnt);
            g_count = 0u;
            __threadfence();
        }
    }
}

extern "C" void kernel_launch(void* const* d_in, const int* in_sizes, int n_in,
                              void* d_out, int out_size)
{
    const float* y_pred = (const float*)d_in[0];
    const float* y_true = (const float*)d_in[1];
    float* out = (float*)d_out;

    const int B     = in_sizes[0] / N_SAMP;              // 16
    const int tiles = (NP1 + T_OUT - 1) / T_OUT;         // 126

    k_fused<<<dim3(tiles, B), NTHR>>>(y_pred, y_true, out, B,
                                      1.0 / ((double)B * (double)NP1));
}

// round 14
// speedup vs baseline: 1.0273x; 1.0273x over previous
#include <cuda_runtime.h>
#include <cuda_fp16.h>
#include <cstdint>

// Problem constants (16 clips of 10 s @ 48 kHz)
#define N_SAMP  480000
#define NP1     480001          // envelope length per row
#define WIN     240             // 5 ms box filter
#define EPSF    1e-6f
#define EPSW    (240.0f * 1e-6f)   // eps on raw window sums
#define LN2     0.6931471805599453

// Tiling: 256 threads, 16 d-elements each; window offset 240 = 15 thread slots.
#define NTHR    256
#define EPT     16
#define T_OUT   3840            // envelope outputs per block (threads 0..239 x 16)
#define L_DV    (T_OUT + WIN - 1)   // 4079 valid d elements per tile
#define MAXB    16

// Scratch (zero-initialized at load; reset by last block each run)
struct RowAcc { double s1, s2; int m; int pad[3]; };
__device__ RowAcc       g_acc[MAXB];
__device__ unsigned int g_count;

struct SMF {
    float   baseP[NTHR], baseT[NTHR];   // per-thread exclusive prefix bases (fp32)
    __half2 h2P[NTHR * 9];              // local inclusive prefixes, idx 9t+k (CF)
    __half2 h2T[NTHR * 9];
    float   wsP[8], wsT[8];
    float   red1[8], red2[8], red3[8];
    double  fin[MAXB];
    int     flag;
};

// Both signals' diffs. All 8 LDG.128 + 2 halo LDG issued before dependent math.
// Packs run pairs to smem as produced (registers stay transient).
// d[m]=|x[id]-x[id-1]|, id=j0-120+m, m in [m0,m0+16).
template<bool INTERIOR>
__device__ __forceinline__ void diffs2(const float* __restrict__ xp,
                                       const float* __restrict__ xt,
                                       int j0, int m0, int lane,
                                       __half2* __restrict__ rp,   // &h2P[9t]
                                       __half2* __restrict__ rt,   // &h2T[9t]
                                       float& sP, float& sT)
{
    if (INTERIOR) {
        float hP = 0.f, hT = 0.f;
        if (lane == 0) { hP = xp[j0 - 121 + m0]; hT = xt[j0 - 121 + m0]; }
        const float4* p4 = reinterpret_cast<const float4*>(xp + (j0 - 120 + m0));
        const float4* q4 = reinterpret_cast<const float4*>(xt + (j0 - 120 + m0));
        float4 A0 = p4[0], A1 = p4[1], A2 = p4[2], A3 = p4[3];
        float4 B0 = q4[0], B1 = q4[1], B2 = q4[2], B3 = q4[3];
        float eP[EPT] = { A0.x, A0.y, A0.z, A0.w,  A1.x, A1.y, A1.z, A1.w,
                          A2.x, A2.y, A2.z, A2.w,  A3.x, A3.y, A3.z, A3.w };
        float eT[EPT] = { B0.x, B0.y, B0.z, B0.w,  B1.x, B1.y, B1.z, B1.w,
                          B2.x, B2.y, B2.z, B2.w,  B3.x, B3.y, B3.z, B3.w };
        float pP = __shfl_up_sync(0xffffffffu, A3.w, 1);
        float pT = __shfl_up_sync(0xffffffffu, B3.w, 1);
        if (lane == 0) { pP = hP; pT = hT; }
        sP = 0.f; sT = 0.f;
        #pragma unroll
        for (int k = 0; k < 8; k++) {
            float aP = sP + fabsf(eP[2 * k] - pP);
            float bP = aP + fabsf(eP[2 * k + 1] - eP[2 * k]);
            rp[k] = __floats2half2_rn(aP, bP);
            pP = eP[2 * k + 1]; sP = bP;
            float aT = sT + fabsf(eT[2 * k] - pT);
            float bT = aT + fabsf(eT[2 * k + 1] - eT[2 * k]);
            rt[k] = __floats2half2_rn(aT, bT);
            pT = eT[2 * k + 1]; sT = bT;
        }
    } else {
        float pP, pT;
        {
            int i = j0 - 121 + m0;
            bool v = (i >= 0 && i < N_SAMP);
            pP = v ? xp[i] : 0.f;
            pT = v ? xt[i] : 0.f;
        }
        sP = 0.f; sT = 0.f;
        #pragma unroll
        for (int k = 0; k < 8; k++) {
            float aP, bP, aT, bT;
            #pragma unroll
            for (int h = 0; h < 2; h++) {
                int c = 2 * k + h;
                int i = j0 - 120 + m0 + c;          // x index == d index
                bool v  = (i >= 0 && i < N_SAMP);
                float cP = v ? xp[i] : 0.f;
                float cT = v ? xt[i] : 0.f;
                bool ok = (i >= 1) && (i < N_SAMP) && (m0 + c < L_DV);
                sP += ok ? fabsf(cP - pP) : 0.f; pP = cP;
                sT += ok ? fabsf(cT - pT) : 0.f; pT = cT;
                if (h == 0) { aP = sP; aT = sT; } else { bP = sP; bT = sT; }
            }
            rp[k] = __floats2half2_rn(aP, bP);
            rt[k] = __floats2half2_rn(aT, bT);
        }
    }
}

__global__ __launch_bounds__(NTHR, 5)
void k_fused(const float* __restrict__ y_pred, const float* __restrict__ y_true,
             float* __restrict__ out, int B, double invcnt)
{
    __shared__ SMF sm;
    const int t = threadIdx.x, lane = t & 31, wid = t >> 5;
    const int row = blockIdx.y;
    const int j0  = blockIdx.x * T_OUT;
    const float* xp = y_pred + (size_t)row * N_SAMP;
    const float* xt = y_true + (size_t)row * N_SAMP;

    const bool interior = (blockIdx.x >= 1) && (blockIdx.x + 2 < gridDim.x);

    float sP, sT;
    if (interior)
        diffs2<true >(xp, xt, j0, t * EPT, lane, &sm.h2P[9 * t], &sm.h2T[9 * t], sP, sT);
    else
        diffs2<false>(xp, xt, j0, t * EPT, lane, &sm.h2P[9 * t], &sm.h2T[9 * t], sP, sT);

    // ---- One interleaved warp scan (two independent chains) ----
    float vP = sP, vT = sT;
    #pragma unroll
    for (int off = 1; off < 32; off <<= 1) {
        float uP = __shfl_up_sync(0xffffffffu, vP, off);
        float uT = __shfl_up_sync(0xffffffffu, vT, off);
        if (lane >= off) { vP += uP; vT += uT; }
    }
    if (lane == 31) { sm.wsP[wid] = vP; sm.wsT[wid] = vT; }
    __syncthreads();

    float baseP = vP - sP, baseT = vT - sT;
    #pragma unroll
    for (int w = 0; w < 7; w++)
        if (w < wid) { baseP += sm.wsP[w]; baseT += sm.wsT[w]; }
    sm.baseP[t] = baseP;
    sm.baseT[t] = baseT;
    __syncthreads();

    // ---- Env + loss: S[c] = (bN - bO) + (runN[c-1] - runO[c-1]) ----
    float s1 = 0.f, s2 = 0.f, mx = 0.f;
    if (t < T_OUT / EPT) {                          // t < 240
        const float DBP = sm.baseP[t + 15] - baseP;
        const float DBT = sm.baseT[t + 15] - baseT;
        float dP[EPT], dT[EPT];                     // dX[c] = runN[c-1]-runO[c-1]
        dP[0] = 0.f; dT[0] = 0.f;
        {
            const __half2* qp = &sm.h2P[9 * (t + 15)];  // neighbor (stride 9: CF)
            const __half2* op = &sm.h2P[9 * t];         // own
            const __half2* qt = &sm.h2T[9 * (t + 15)];
            const __half2* ot = &sm.h2T[9 * t];
            #pragma unroll
            for (int k = 0; k < 8; k++) {
                float2 fp = __half22float2(__hsub2(qp[k], op[k]));
                float2 ft = __half22float2(__hsub2(qt[k], ot[k]));
                dP[2 * k + 1] = fp.x;
                dT[2 * k + 1] = ft.x;
                if (k < 7) { dP[2 * k + 2] = fp.y; dT[2 * k + 2] = ft.y; }
            }
        }
        #pragma unroll
        for (int c = 0; c < EPT; c++) {
            if (interior || (j0 + t * EPT + c < NP1)) {
                float Sp = DBP + dP[c];
                float St = DBT + dT[c];
                float df = fabsf(__log2f(Sp + EPSW) - __log2f(St + EPSW));
                s1 += df; s2 += df * St; mx = fmaxf(mx, St);
            }
        }
    }

    // ---- Block reduction of (S1, S2, M) ----
    #pragma unroll
    for (int off = 16; off > 0; off >>= 1) {
        s1 += __shfl_down_sync(0xffffffffu, s1, off);
        s2 += __shfl_down_sync(0xffffffffu, s2, off);
        mx  = fmaxf(mx, __shfl_down_sync(0xffffffffu, mx, off));
    }
    if (lane == 0) { sm.red1[wid] = s1; sm.red2[wid] = s2; sm.red3[wid] = mx; }
    __syncthreads();

    if (t == 0) {
        float a1 = 0.f, a2 = 0.f, am = 0.f;
        #pragma unroll
        for (int w = 0; w < 8; w++) {
            a1 += sm.red1[w]; a2 += sm.red2[w]; am = fmaxf(am, sm.red3[w]);
        }
        atomicAdd(&g_acc[row].s1, (double)a1 * LN2);   // log2 -> ln
        atomicAdd(&g_acc[row].s2, (double)a2 * LN2);
        atomicMax(&g_acc[row].m, __float_as_int(am));  // raw window-sum max, >= 0
        __threadfence();

        unsigned int total = gridDim.x * gridDim.y;
        unsigned int old = atomicAdd(&g_count, 1u);
        sm.flag = (old == total - 1u) ? 1 : 0;
    }
    __syncthreads();

    if (sm.flag) {
        // Last block: finalize in parallel, reset scratch for next replay.
        __threadfence();
        if (t < B) {
            volatile double* p1 = &g_acc[t].s1;
            volatile double* p2 = &g_acc[t].s2;
            volatile int*    pm = &g_acc[t].m;
            double S1 = *p1;                   // sum df            (true scale)
            double S2 = *p2;                   // sum df * S_t      (240x scale)
            float  M  = __int_as_float(*pm);   // 240 * true max
            sm.fin[t] = 0.2 * S1 + 0.8 * S2 / ((double)M + (double)EPSW);
            g_acc[t].s1 = 0.0; g_acc[t].s2 = 0.0; g_acc[t].m = 0;
        }
        __syncthreads();
        if (t == 0) {
            double tot = 0.0;
            for (int r = 0; r < B; r++) tot += sm.fin[r];
            out[0] = (float)(tot * invcnt);
            g_count = 0u;
            __threadfence();
        }
    }
}

extern "C" void kernel_launch(void* const* d_in, const int* in_sizes, int n_in,
                              void* d_out, int out_size)
{
    const float* y_pred = (const float*)d_in[0];
    const float* y_true = (const float*)d_in[1];
    float* out = (float*)d_out;

    const int B     = in_sizes[0] / N_SAMP;              // 16
    const int tiles = (NP1 + T_OUT - 1) / T_OUT;         // 126

    k_fused<<<dim3(tiles, B), NTHR>>>(y_pred, y_true, out, B,
                                      1.0 / ((double)B * (double)NP1));
}